// round 7
// baseline (speedup 1.0000x reference)
#include <cuda_runtime.h>
#include <stdint.h>

#define N_BCH 8
#define N_ATM 10000
#define N_ELM 100
#define THREADS 256
#define GRID_MAIN 296            // 2 CTAs per SM (148 SMs)

#define ELM_BYTES (N_BCH * N_ATM)               // 80000
// smem layout (bytes): two acc regions to break RMW aliasing chains
#define SMEM_ACC0  0                            // 8*256 floats = 8192
#define SMEM_ACC1  (8 * THREADS * 4)            // 8192
#define SMEM_LUT   (16 * THREADS * 4)           // 128 float2 = 1024
#define SMEM_ELM   (SMEM_LUT + 1024)
#define SMEM_TOTAL (SMEM_ELM + ELM_BYTES)       // 97408 B -> 2 CTAs/SM

__device__ uint8_t g_elm8[ELM_BYTES];

__device__ __forceinline__ float fsqrt_approx(float x)
{
    float y;
    asm("sqrt.approx.f32 %0, %1;" : "=f"(y) : "f"(x));
    return y;
}

// ---------------------------------------------------------------------------
// Prepass: zero outputs, convert elm int32 -> uint8 (values < 100).
// ---------------------------------------------------------------------------
__global__ void prep_kernel(const int* __restrict__ elm, float* __restrict__ out)
{
    int tid = blockIdx.x * blockDim.x + threadIdx.x;
    if (tid < N_BCH) out[tid] = 0.0f;
    for (int i = tid; i < ELM_BYTES; i += gridDim.x * blockDim.x)
        g_elm8[i] = (uint8_t)elm[i];
}

// ---------------------------------------------------------------------------
// Per-edge work: smem gathers + smem RMW into the given acc region.
// ---------------------------------------------------------------------------
__device__ __forceinline__ void edge_op(int n, int i, int j, float s,
                                        const uint8_t* __restrict__ elm_s,
                                        const float2* __restrict__ lut,
                                        float* __restrict__ acc_base)
{
    int ea = elm_s[n * N_ATM + i];
    int eb = elm_s[n * N_ATM + j];
    float2 pa = lut[ea];
    float2 pb = lut[eb];
    float R   = pa.y + pb.y;
    float dis = fsqrt_approx(s);
    if (dis < R) {
        float d = dis - R;
        acc_base[n << 5] += (pa.x + pb.x) * d * d;
    }
}

__global__ void __launch_bounds__(THREADS, 2)
close_penalty_kernel(const int4*  __restrict__ edge_n4,
                     const int4*  __restrict__ edge_i4,
                     const int4*  __restrict__ edge_j4,
                     const float4* __restrict__ sod4,
                     const int*   __restrict__ edge_n,
                     const int*   __restrict__ edge_i,
                     const int*   __restrict__ edge_j,
                     const float* __restrict__ sod,
                     const float* __restrict__ k,
                     const float* __restrict__ radius,
                     float* __restrict__ out,
                     int nvec, int E)
{
    extern __shared__ char smem[];
    float*   acc0  = (float*)  (smem + SMEM_ACC0);
    float*   acc1  = (float*)  (smem + SMEM_ACC1);
    float2*  lut   = (float2*) (smem + SMEM_LUT);
    uint8_t* elm_s = (uint8_t*)(smem + SMEM_ELM);

    int tid  = threadIdx.x;
    int lane = tid & 31;
    int wid  = tid >> 5;

    if (tid < N_ELM) lut[tid] = make_float2(__ldg(&k[tid]), __ldg(&radius[tid]));
    #pragma unroll
    for (int b = 0; b < 8; b++) {
        acc0[b * THREADS + tid] = 0.0f;
        acc1[b * THREADS + tid] = 0.0f;
    }

    // Copy 80 KB u8 element table into shared memory (16B chunks).
    {
        const int4* src = (const int4*)g_elm8;
        int4*       dst = (int4*)elm_s;
        for (int i = tid; i < ELM_BYTES / 16; i += THREADS)
            dst[i] = __ldg(&src[i]);
    }
    __syncthreads();

    float* acc_base0 = &acc0[(wid << 8) | lane];
    float* acc_base1 = &acc1[(wid << 8) | lane];

    int gtid   = blockIdx.x * blockDim.x + tid;
    int stride = gridDim.x * blockDim.x;

    int v = gtid;
    // 2x unrolled; PLAIN loads so repeated graph replays stay L2-resident.
    for (; v + stride < nvec; v += 2 * stride) {
        int v2 = v + stride;
        int4   en0 = edge_n4[v];
        int4   ei0 = edge_i4[v];
        int4   ej0 = edge_j4[v];
        float4 s0  = sod4[v];
        int4   en1 = edge_n4[v2];
        int4   ei1 = edge_i4[v2];
        int4   ej1 = edge_j4[v2];
        float4 s1  = sod4[v2];

        // Alternate acc regions so consecutive RMWs never alias.
        edge_op(en0.x, ei0.x, ej0.x, s0.x, elm_s, lut, acc_base0);
        edge_op(en0.y, ei0.y, ej0.y, s0.y, elm_s, lut, acc_base1);
        edge_op(en0.z, ei0.z, ej0.z, s0.z, elm_s, lut, acc_base0);
        edge_op(en0.w, ei0.w, ej0.w, s0.w, elm_s, lut, acc_base1);
        edge_op(en1.x, ei1.x, ej1.x, s1.x, elm_s, lut, acc_base0);
        edge_op(en1.y, ei1.y, ej1.y, s1.y, elm_s, lut, acc_base1);
        edge_op(en1.z, ei1.z, ej1.z, s1.z, elm_s, lut, acc_base0);
        edge_op(en1.w, ei1.w, ej1.w, s1.w, elm_s, lut, acc_base1);
    }
    for (; v < nvec; v += stride) {
        int4   en = edge_n4[v];
        int4   ei = edge_i4[v];
        int4   ej = edge_j4[v];
        float4 s  = sod4[v];
        edge_op(en.x, ei.x, ej.x, s.x, elm_s, lut, acc_base0);
        edge_op(en.y, ei.y, ej.y, s.y, elm_s, lut, acc_base1);
        edge_op(en.z, ei.z, ej.z, s.z, elm_s, lut, acc_base0);
        edge_op(en.w, ei.w, ej.w, s.w, elm_s, lut, acc_base1);
    }

    // Scalar tail
    int t = nvec * 4 + gtid;
    if (t < E)
        edge_op(edge_n[t], edge_i[t], edge_j[t], sod[t], elm_s, lut, acc_base0);

    __syncthreads();

    // Reduce: thread owns (bin = tid>>5, lane); sum both regions over 8 warps.
    int bin = tid >> 5;
    float sum = 0.0f;
    #pragma unroll
    for (int w = 0; w < 8; w++) {
        sum += acc0[(w << 8) + (bin << 5) + lane];
        sum += acc1[(w << 8) + (bin << 5) + lane];
    }
    #pragma unroll
    for (int off = 16; off > 0; off >>= 1)
        sum += __shfl_down_sync(0xFFFFFFFFu, sum, off);
    if (lane == 0)
        atomicAdd(&out[bin], sum);
}

// ---------------------------------------------------------------------------
// Launch
// ---------------------------------------------------------------------------
extern "C" void kernel_launch(void* const* d_in, const int* in_sizes, int n_in,
                              void* d_out, int out_size)
{
    const int*   elm    = (const int*)  d_in[0];
    const int*   edge_n = (const int*)  d_in[1];
    const int*   edge_i = (const int*)  d_in[2];
    const int*   edge_j = (const int*)  d_in[3];
    const float* sod    = (const float*)d_in[4];
    const float* k      = (const float*)d_in[5];
    const float* radius = (const float*)d_in[6];
    float* out = (float*)d_out;

    int E    = in_sizes[1];
    int nvec = E >> 2;

    cudaFuncSetAttribute(close_penalty_kernel,
                         cudaFuncAttributeMaxDynamicSharedMemorySize, SMEM_TOTAL);

    prep_kernel<<<(ELM_BYTES + 255) / 256, 256>>>(elm, out);

    int grid = GRID_MAIN;
    int need = (nvec + THREADS - 1) / THREADS;
    if (need < grid) grid = need > 0 ? need : 1;

    close_penalty_kernel<<<grid, THREADS, SMEM_TOTAL>>>(
        (const int4*)edge_n, (const int4*)edge_i, (const int4*)edge_j,
        (const float4*)sod,
        edge_n, edge_i, edge_j, sod,
        k, radius,
        out, nvec, E);
}

// round 8
// speedup vs baseline: 1.0094x; 1.0094x over previous
#include <cuda_runtime.h>
#include <stdint.h>

#define N_BCH 8
#define N_ATM 10000
#define N_ELM 100
#define THREADS 256
#define GRID_MAIN 296            // 2 CTAs per SM (148 SMs)

#define ELM_BYTES (N_BCH * N_ATM)               // 80000
// smem layout (bytes)
#define SMEM_ACC   0                            // 8*256 floats = 8192
#define SMEM_LUT   (8 * THREADS * 4)            // 128 float2 = 1024
#define SMEM_ELM   (SMEM_LUT + 1024)
#define SMEM_TOTAL (SMEM_ELM + ELM_BYTES)       // 89216 B -> 2 CTAs/SM

__device__ uint8_t g_elm8[ELM_BYTES];

__device__ __forceinline__ float fsqrt_approx(float x)
{
    float y;
    asm("sqrt.approx.f32 %0, %1;" : "=f"(y) : "f"(x));
    return y;
}

// ---------------------------------------------------------------------------
// Prepass: zero outputs, convert elm int32 -> uint8 (values < 100).
// ---------------------------------------------------------------------------
__global__ void prep_kernel(const int* __restrict__ elm, float* __restrict__ out)
{
    int tid = blockIdx.x * blockDim.x + threadIdx.x;
    if (tid < N_BCH) out[tid] = 0.0f;
    for (int i = tid; i < ELM_BYTES; i += gridDim.x * blockDim.x)
        g_elm8[i] = (uint8_t)elm[i];
}

// ---------------------------------------------------------------------------
// Per-edge work: smem gathers + smem RMW accumulate.
// ---------------------------------------------------------------------------
__device__ __forceinline__ void edge_op(int n, int i, int j, float s,
                                        const uint8_t* __restrict__ elm_s,
                                        const float2* __restrict__ lut,
                                        float* __restrict__ acc_base)
{
    int ea = elm_s[n * N_ATM + i];
    int eb = elm_s[n * N_ATM + j];
    float2 pa = lut[ea];
    float2 pb = lut[eb];
    float R   = pa.y + pb.y;
    float dis = fsqrt_approx(s);
    if (dis < R) {
        float d = dis - R;
        acc_base[n << 5] += (pa.x + pb.x) * d * d;
    }
}

__global__ void __launch_bounds__(THREADS, 2)
close_penalty_kernel(const int4*  __restrict__ edge_n4,
                     const int4*  __restrict__ edge_i4,
                     const int4*  __restrict__ edge_j4,
                     const float4* __restrict__ sod4,
                     const int*   __restrict__ edge_n,
                     const int*   __restrict__ edge_i,
                     const int*   __restrict__ edge_j,
                     const float* __restrict__ sod,
                     const float* __restrict__ k,
                     const float* __restrict__ radius,
                     float* __restrict__ out,
                     int nvec, int E)
{
    extern __shared__ char smem[];
    float*   acc   = (float*)  (smem + SMEM_ACC);
    float2*  lut   = (float2*) (smem + SMEM_LUT);
    uint8_t* elm_s = (uint8_t*)(smem + SMEM_ELM);

    int tid  = threadIdx.x;
    int lane = tid & 31;
    int wid  = tid >> 5;

    if (tid < N_ELM) lut[tid] = make_float2(__ldg(&k[tid]), __ldg(&radius[tid]));
    #pragma unroll
    for (int b = 0; b < 8; b++) acc[b * THREADS + tid] = 0.0f;

    // Copy 80 KB u8 element table into shared memory (16B chunks).
    {
        const int4* src = (const int4*)g_elm8;
        int4*       dst = (int4*)elm_s;
        for (int i = tid; i < ELM_BYTES / 16; i += THREADS)
            dst[i] = __ldg(&src[i]);
    }
    __syncthreads();

    float* acc_base = &acc[(wid << 8) | lane];   // + (n<<5) per edge

    int gtid   = blockIdx.x * blockDim.x + tid;
    int stride = gridDim.x * blockDim.x;

    // -------------------- software-pipelined main loop --------------------
    int v = gtid;
    if (v < nvec) {
        // prologue: load batch(v)
        int4   enC = __ldcs(&edge_n4[v]);
        int4   eiC = __ldcs(&edge_i4[v]);
        int4   ejC = __ldcs(&edge_j4[v]);
        float4 sC  = __ldcs(&sod4[v]);

        for (; v + stride < nvec; v += stride) {
            int vn = v + stride;
            // issue next batch's loads BEFORE consuming current batch
            int4   enN = __ldcs(&edge_n4[vn]);
            int4   eiN = __ldcs(&edge_i4[vn]);
            int4   ejN = __ldcs(&edge_j4[vn]);
            float4 sN  = __ldcs(&sod4[vn]);

            edge_op(enC.x, eiC.x, ejC.x, sC.x, elm_s, lut, acc_base);
            edge_op(enC.y, eiC.y, ejC.y, sC.y, elm_s, lut, acc_base);
            edge_op(enC.z, eiC.z, ejC.z, sC.z, elm_s, lut, acc_base);
            edge_op(enC.w, eiC.w, ejC.w, sC.w, elm_s, lut, acc_base);

            enC = enN; eiC = eiN; ejC = ejN; sC = sN;
        }
        // epilogue: consume last batch
        edge_op(enC.x, eiC.x, ejC.x, sC.x, elm_s, lut, acc_base);
        edge_op(enC.y, eiC.y, ejC.y, sC.y, elm_s, lut, acc_base);
        edge_op(enC.z, eiC.z, ejC.z, sC.z, elm_s, lut, acc_base);
        edge_op(enC.w, eiC.w, ejC.w, sC.w, elm_s, lut, acc_base);
    }

    // Scalar tail
    int t = nvec * 4 + gtid;
    if (t < E)
        edge_op(edge_n[t], edge_i[t], edge_j[t], sod[t], elm_s, lut, acc_base);

    __syncthreads();

    // Reduce: thread owns (bin = tid>>5, lane); sum over 8 warps, shuffle-reduce.
    int bin = tid >> 5;
    float sum = 0.0f;
    #pragma unroll
    for (int w = 0; w < 8; w++)
        sum += acc[(w << 8) + (bin << 5) + lane];
    #pragma unroll
    for (int off = 16; off > 0; off >>= 1)
        sum += __shfl_down_sync(0xFFFFFFFFu, sum, off);
    if (lane == 0)
        atomicAdd(&out[bin], sum);
}

// ---------------------------------------------------------------------------
// Launch
// ---------------------------------------------------------------------------
extern "C" void kernel_launch(void* const* d_in, const int* in_sizes, int n_in,
                              void* d_out, int out_size)
{
    const int*   elm    = (const int*)  d_in[0];
    const int*   edge_n = (const int*)  d_in[1];
    const int*   edge_i = (const int*)  d_in[2];
    const int*   edge_j = (const int*)  d_in[3];
    const float* sod    = (const float*)d_in[4];
    const float* k      = (const float*)d_in[5];
    const float* radius = (const float*)d_in[6];
    float* out = (float*)d_out;

    int E    = in_sizes[1];
    int nvec = E >> 2;

    cudaFuncSetAttribute(close_penalty_kernel,
                         cudaFuncAttributeMaxDynamicSharedMemorySize, SMEM_TOTAL);

    prep_kernel<<<(ELM_BYTES + 255) / 256, 256>>>(elm, out);

    int grid = GRID_MAIN;
    int need = (nvec + THREADS - 1) / THREADS;
    if (need < grid) grid = need > 0 ? need : 1;

    close_penalty_kernel<<<grid, THREADS, SMEM_TOTAL>>>(
        (const int4*)edge_n, (const int4*)edge_i, (const int4*)edge_j,
        (const float4*)sod,
        edge_n, edge_i, edge_j, sod,
        k, radius,
        out, nvec, E);
}

// round 9
// speedup vs baseline: 1.0906x; 1.0804x over previous
#include <cuda_runtime.h>
#include <stdint.h>

#define N_BCH 8
#define N_ATM 10000
#define N_ELM 100
#define THREADS 512
#define NWARP  16
#define GRID_MAIN 148            // 1 CTA per SM
#define STAGES 3

#define ELM_BYTES (N_BCH * N_ATM)               // 80000
// smem layout (bytes)
#define SMEM_ACC   0                            // 16 warps * 256 floats = 16384
#define SMEM_LUT   (NWARP * 256 * 4)            // 1024
#define SMEM_ELM   (SMEM_LUT + 1024)            // 80000 -> ends 97408
#define SMEM_BUF   (SMEM_ELM + ELM_BYTES)       // 3 stages * 4 arrays * 512 * 16B = 98304
#define SMEM_TOTAL (SMEM_BUF + STAGES * 4 * THREADS * 16)   // 195712 B

__device__ uint8_t g_elm8[ELM_BYTES];

__device__ __forceinline__ float fsqrt_approx(float x)
{
    float y;
    asm("sqrt.approx.f32 %0, %1;" : "=f"(y) : "f"(x));
    return y;
}

__device__ __forceinline__ void cp16(uint32_t saddr, const void* gptr)
{
    asm volatile("cp.async.cg.shared.global [%0], [%1], 16;\n"
                 :: "r"(saddr), "l"(gptr));
}
__device__ __forceinline__ void cp_commit()
{
    asm volatile("cp.async.commit_group;\n");
}
template <int N>
__device__ __forceinline__ void cp_wait()
{
    asm volatile("cp.async.wait_group %0;\n" :: "n"(N));
}

__device__ __forceinline__ uint32_t smem_u32(const void* p)
{
    uint32_t a;
    asm("{ .reg .u64 t; cvta.to.shared.u64 t, %1; cvt.u32.u64 %0, t; }"
        : "=r"(a) : "l"(p));
    return a;
}

// ---------------------------------------------------------------------------
// Prepass: zero outputs, convert elm int32 -> uint8 (values < 100).
// ---------------------------------------------------------------------------
__global__ void prep_kernel(const int* __restrict__ elm, float* __restrict__ out)
{
    int tid = blockIdx.x * blockDim.x + threadIdx.x;
    if (tid < N_BCH) out[tid] = 0.0f;
    for (int i = tid; i < ELM_BYTES; i += gridDim.x * blockDim.x)
        g_elm8[i] = (uint8_t)elm[i];
}

// ---------------------------------------------------------------------------
// Per-edge work: smem gathers + smem RMW accumulate.
// ---------------------------------------------------------------------------
__device__ __forceinline__ void edge_op(int n, int i, int j, float s,
                                        const uint8_t* __restrict__ elm_s,
                                        const float2* __restrict__ lut,
                                        float* __restrict__ acc_base)
{
    int ea = elm_s[n * N_ATM + i];
    int eb = elm_s[n * N_ATM + j];
    float2 pa = lut[ea];
    float2 pb = lut[eb];
    float R   = pa.y + pb.y;
    float dis = fsqrt_approx(s);
    if (dis < R) {
        float d = dis - R;
        acc_base[n << 5] += (pa.x + pb.x) * d * d;
    }
}

__global__ void __launch_bounds__(THREADS, 1)
close_penalty_kernel(const int4*  __restrict__ edge_n4,
                     const int4*  __restrict__ edge_i4,
                     const int4*  __restrict__ edge_j4,
                     const float4* __restrict__ sod4,
                     const int*   __restrict__ edge_n,
                     const int*   __restrict__ edge_i,
                     const int*   __restrict__ edge_j,
                     const float* __restrict__ sod,
                     const float* __restrict__ k,
                     const float* __restrict__ radius,
                     float* __restrict__ out,
                     int nvec, int E)
{
    extern __shared__ char smem[];
    float*   acc   = (float*)  (smem + SMEM_ACC);
    float2*  lut   = (float2*) (smem + SMEM_LUT);
    uint8_t* elm_s = (uint8_t*)(smem + SMEM_ELM);
    char*    buf   = smem + SMEM_BUF;           // [stage][array][tid] 16B slots

    int tid  = threadIdx.x;
    int lane = tid & 31;
    int wid  = tid >> 5;

    if (tid < N_ELM) lut[tid] = make_float2(__ldg(&k[tid]), __ldg(&radius[tid]));
    #pragma unroll
    for (int b = 0; b < 8; b++) acc[b * THREADS + tid] = 0.0f;

    // Copy 80 KB u8 element table into shared memory (16B chunks).
    {
        const int4* src = (const int4*)g_elm8;
        int4*       dst = (int4*)elm_s;
        for (int i = tid; i < ELM_BYTES / 16; i += THREADS)
            dst[i] = __ldg(&src[i]);
    }
    __syncthreads();

    float* acc_base = &acc[(wid << 8) | lane];   // + (n<<5) per edge

    // Per-thread stage slot addresses (shared-space u32 for cp.async).
    uint32_t my_slot = smem_u32(buf) + (uint32_t)tid * 16;
    const uint32_t ARR = THREADS * 16;           // bytes per array within a stage
    const uint32_t STG = 4 * ARR;                // bytes per stage

    int nblk = (nvec + THREADS - 1) / THREADS;   // blocks of 512 vec4 groups

    // ---- stage(blk, s): issue 4 cp.asyncs for this thread's element ----
    auto stage = [&](int blk, int s) {
        long base = (long)blk * THREADS + tid;
        if (blk < nblk && base < nvec) {
            uint32_t so = my_slot + (uint32_t)s * STG;
            cp16(so + 0 * ARR, &edge_n4[base]);
            cp16(so + 1 * ARR, &edge_i4[base]);
            cp16(so + 2 * ARR, &edge_j4[base]);
            cp16(so + 3 * ARR, &sod4[base]);
        }
    };

    // Prologue: fill STAGES-1 stages.
    #pragma unroll
    for (int p = 0; p < STAGES - 1; p++) {
        stage(blockIdx.x + p * gridDim.x, p);
        cp_commit();
    }

    // Main pipelined loop: prefetch it+STAGES-1 while consuming it.
    for (int it = 0; ; it++) {
        int blk_cons = blockIdx.x + it * gridDim.x;
        if (blk_cons >= nblk) break;

        stage(blockIdx.x + (it + STAGES - 1) * gridDim.x,
              (it + STAGES - 1) % STAGES);
        cp_commit();
        cp_wait<STAGES - 1>();   // oldest group (ours to consume) is done

        long base = (long)blk_cons * THREADS + tid;
        if (base < nvec) {
            int s = it % STAGES;
            const char* sp = buf + (size_t)s * STG + (size_t)tid * 16;
            int4   en = *(const int4*)  (sp + 0 * ARR);
            int4   ei = *(const int4*)  (sp + 1 * ARR);
            int4   ej = *(const int4*)  (sp + 2 * ARR);
            float4 sd = *(const float4*)(sp + 3 * ARR);

            edge_op(en.x, ei.x, ej.x, sd.x, elm_s, lut, acc_base);
            edge_op(en.y, ei.y, ej.y, sd.y, elm_s, lut, acc_base);
            edge_op(en.z, ei.z, ej.z, sd.z, elm_s, lut, acc_base);
            edge_op(en.w, ei.w, ej.w, sd.w, elm_s, lut, acc_base);
        }
    }
    cp_wait<0>();

    // Scalar tail
    int gtid = blockIdx.x * THREADS + tid;
    int t = nvec * 4 + gtid;
    if (t < E)
        edge_op(edge_n[t], edge_i[t], edge_j[t], sod[t], elm_s, lut, acc_base);

    __syncthreads();

    // Reduce: first 256 threads; thread owns (bin = tid>>5, lane).
    if (tid < 256) {
        int bin = tid >> 5;
        float sum = 0.0f;
        #pragma unroll
        for (int w = 0; w < NWARP; w++)
            sum += acc[(w << 8) + (bin << 5) + lane];
        #pragma unroll
        for (int off = 16; off > 0; off >>= 1)
            sum += __shfl_down_sync(0xFFFFFFFFu, sum, off);
        if (lane == 0)
            atomicAdd(&out[bin], sum);
    }
}

// ---------------------------------------------------------------------------
// Launch
// ---------------------------------------------------------------------------
extern "C" void kernel_launch(void* const* d_in, const int* in_sizes, int n_in,
                              void* d_out, int out_size)
{
    const int*   elm    = (const int*)  d_in[0];
    const int*   edge_n = (const int*)  d_in[1];
    const int*   edge_i = (const int*)  d_in[2];
    const int*   edge_j = (const int*)  d_in[3];
    const float* sod    = (const float*)d_in[4];
    const float* k      = (const float*)d_in[5];
    const float* radius = (const float*)d_in[6];
    float* out = (float*)d_out;

    int E    = in_sizes[1];
    int nvec = E >> 2;

    cudaFuncSetAttribute(close_penalty_kernel,
                         cudaFuncAttributeMaxDynamicSharedMemorySize, SMEM_TOTAL);

    prep_kernel<<<(ELM_BYTES + 255) / 256, 256>>>(elm, out);

    int grid = GRID_MAIN;
    int nblk = (nvec + THREADS - 1) / THREADS;
    if (nblk < grid) grid = nblk > 0 ? nblk : 1;

    close_penalty_kernel<<<grid, THREADS, SMEM_TOTAL>>>(
        (const int4*)edge_n, (const int4*)edge_i, (const int4*)edge_j,
        (const float4*)sod,
        edge_n, edge_i, edge_j, sod,
        k, radius,
        out, nvec, E);
}